// round 16
// baseline (speedup 1.0000x reference)
#include <cuda_runtime.h>
#include <cuda_bf16.h>
#include <cstdint>

// ---------------- problem constants ----------------
#define BROWS 16384
#define DIN   512
#define NSP   26
#define EMB   128
#define OUTD  512
#define NI    27
#define NTRI  378
#define KAP   1792
#define ALO   896
#define KWO   1792          // Wo pack: [hi(896) | lo(896)]
#define KWP   1024          // Wp pack: [hi(512) | lo(512)]

// ---------------- device scratch (ONLY referenced from device code!) --------
__device__ __align__(16) __nv_bfloat16 g_apack[BROWS * KAP];
__device__ __align__(16) __nv_bfloat16 g_wopack[OUTD * KWO];
__device__ __align__(16) __nv_bfloat16 g_wppack[EMB * KWP];
__device__ __align__(16) float         g_proj[BROWS * EMB];

// ---------------- helpers ----------------
__device__ __forceinline__ void bf_split(float v, __nv_bfloat16& h, __nv_bfloat16& l) {
    h = __float2bfloat16(v);
    l = __float2bfloat16(v - __bfloat162float(h));
}
__device__ __forceinline__ uint32_t smem_u32(const void* p) {
    uint32_t a;
    asm("{ .reg .u64 t; cvta.to.shared.u64 t, %1; cvt.u32.u64 %0, t; }" : "=r"(a) : "l"(p));
    return a;
}
__device__ __forceinline__ void cp_async16(uint32_t s, const void* g) {
    asm volatile("cp.async.cg.shared.global [%0], [%1], 16;" :: "r"(s), "l"(g) : "memory");
}
__device__ __forceinline__ void ldsm_x4(uint32_t* r, uint32_t addr) {
    asm volatile("ldmatrix.sync.aligned.m8n8.x4.shared.b16 {%0,%1,%2,%3}, [%4];"
                 : "=r"(r[0]), "=r"(r[1]), "=r"(r[2]), "=r"(r[3]) : "r"(addr));
}
__device__ __forceinline__ void mma16816(float* c,
                                         const uint32_t* a, uint32_t b0, uint32_t b1) {
    asm volatile("mma.sync.aligned.m16n8k16.row.col.f32.bf16.bf16.f32 "
                 "{%0,%1,%2,%3}, {%4,%5,%6,%7}, {%8,%9}, {%0,%1,%2,%3};"
                 : "+f"(c[0]), "+f"(c[1]), "+f"(c[2]), "+f"(c[3])
                 : "r"(a[0]), "r"(a[1]), "r"(a[2]), "r"(a[3]), "r"(b0), "r"(b1));
}

// ---------------------------------------------------------------------------
// pack kernels
// ---------------------------------------------------------------------------
__global__ void pack_dense_kernel(const float* __restrict__ dense) {
    size_t t   = (size_t)blockIdx.x * 256 + threadIdx.x;
    size_t row = t >> 7;
    int    c4  = (int)(t & 127) * 4;
    float4 v   = *(const float4*)(dense + row * DIN + c4);
    float  vv[4] = {v.x, v.y, v.z, v.w};
    __nv_bfloat16 h[4], l[4];
#pragma unroll
    for (int i = 0; i < 4; i++) bf_split(vv[i], h[i], l[i]);
    __nv_bfloat16* a = g_apack + row * KAP;
    *(__nv_bfloat162*)(a + c4)           = __nv_bfloat162(h[0], h[1]);
    *(__nv_bfloat162*)(a + c4 + 2)       = __nv_bfloat162(h[2], h[3]);
    *(__nv_bfloat162*)(a + ALO + c4)     = __nv_bfloat162(l[0], l[1]);
    *(__nv_bfloat162*)(a + ALO + c4 + 2) = __nv_bfloat162(l[2], l[3]);
}

__global__ void pack_wo_kernel(const float* __restrict__ Wo) {
    int n = blockIdx.x;
    for (int k = threadIdx.x; k < 896; k += 256) {
        float v = (k < 890) ? Wo[(size_t)n * 890 + k] : 0.0f;
        __nv_bfloat16 h, l;
        bf_split(v, h, l);
        __nv_bfloat16* w = g_wopack + (size_t)n * KWO;
        w[k] = h; w[896 + k] = l;
    }
}

__global__ void pack_wp_kernel(const float* __restrict__ Wp) {
    int n = blockIdx.x;
    for (int k = threadIdx.x; k < 512; k += 256) {
        float v = Wp[(size_t)n * 512 + k];
        __nv_bfloat16 h, l;
        bf_split(v, h, l);
        __nv_bfloat16* w = g_wppack + (size_t)n * KWP;
        w[k] = h; w[512 + k] = l;
    }
}

// ---------------------------------------------------------------------------
// Unified-chunk HMMA GEMM, register-pipelined fragments.
// 512 threads = 16 warps (4/SMSP), CTA 128x128, warp tile 32x32.
// Per K32 chunk: ldsm(ks0), ldsm(ks1) issued BEFORE mma(ks0) -> in-order issue
// keeps the ks1 smem reads in flight under the ks0 mma burst.
// MODE 0: proj (C=g_proj, ldc=EMB)   MODE 1: out (C=arg, ldc=OUTD)
// ---------------------------------------------------------------------------
#define PADK   40                       // bf16 row stride -> 80B, conflict-free
#define TILE   (128 * PADK)
#define STAGE  (4 * TILE)               // Ahi, Alo, Whi, Wlo
#define SMEM_BYTES (2 * STAGE * 2)      // 81920

template<int SC, int KWH, int MODE>
__global__ void __launch_bounds__(512, 1)
gemm_mma_kernel(const float* __restrict__ bias, float* __restrict__ C_arg)
{
    extern __shared__ __align__(16) __nv_bfloat16 smem[];

    const __nv_bfloat16* __restrict__ A = g_apack;
    const __nv_bfloat16* __restrict__ W = (MODE == 0) ? g_wppack : g_wopack;
    const int KA  = KAP;
    const int KW  = 2 * KWH;
    float* __restrict__ C = (MODE == 0) ? g_proj : C_arg;
    const int ldc = (MODE == 0) ? EMB : OUTD;

    const int tid  = threadIdx.x;
    const int wid  = tid >> 5;
    const int lane = tid & 31;
    const int wm   = wid >> 2;     // 0..3 warp-row (32 rows)
    const int wn   = wid & 3;      // 0..3 warp-col (32 cols)
    const int m0   = blockIdx.y * 128;
    const int n0   = blockIdx.x * 128;

    float acc[2][4][4];
#pragma unroll
    for (int i = 0; i < 2; i++)
#pragma unroll
        for (int j = 0; j < 4; j++)
#pragma unroll
            for (int q = 0; q < 4; q++) acc[i][j][q] = 0.0f;

    // fragment registers, double-buffered across ks windows
    uint32_t ah[2][2][4], al[2][2][4], wh[2][2][4], wl[2][2][4];

    // 2048 uint4 tasks over 512 threads (4 each): tile = batch index
    auto load = [&](int c, int buf) {
        const __nv_bfloat16* sa = A + (size_t)m0 * KA + c * 32;
        const __nv_bfloat16* sw = W + (size_t)n0 * KW + c * 32;
        __nv_bfloat16* dst = smem + buf * STAGE;
        const int row = (tid >> 2) & 127;
        const int j   = tid & 3;
        cp_async16(smem_u32(dst + 0 * TILE + row * PADK + j * 8),
                   sa + (size_t)row * KA + j * 8);
        cp_async16(smem_u32(dst + 1 * TILE + row * PADK + j * 8),
                   sa + (size_t)row * KA + ALO + j * 8);
        cp_async16(smem_u32(dst + 2 * TILE + row * PADK + j * 8),
                   sw + (size_t)row * KW + j * 8);
        cp_async16(smem_u32(dst + 3 * TILE + row * PADK + j * 8),
                   sw + (size_t)row * KW + KWH + j * 8);
        asm volatile("cp.async.commit_group;" ::: "memory");
    };

    auto ldfrags = [&](const __nv_bfloat16* base, int ks, int p) {
        const int aoff = (wm * 32 + (lane & 15)) * PADK + ks * 16 + (lane >> 4) * 8;
        const int boff = (wn * 32 + ((lane >> 4) & 1) * 8 + (lane & 7)) * PADK +
                         ks * 16 + ((lane >> 3) & 1) * 8;
#pragma unroll
        for (int mt = 0; mt < 2; mt++)
            ldsm_x4(ah[p][mt], smem_u32(base + 0 * TILE + aoff + mt * 16 * PADK));
#pragma unroll
        for (int mt = 0; mt < 2; mt++)
            ldsm_x4(al[p][mt], smem_u32(base + 1 * TILE + aoff + mt * 16 * PADK));
#pragma unroll
        for (int n2 = 0; n2 < 2; n2++)
            ldsm_x4(wh[p][n2], smem_u32(base + 2 * TILE + boff + n2 * 16 * PADK));
#pragma unroll
        for (int n2 = 0; n2 < 2; n2++)
            ldsm_x4(wl[p][n2], smem_u32(base + 3 * TILE + boff + n2 * 16 * PADK));
    };

    auto mmas = [&](int p) {
#pragma unroll
        for (int mt = 0; mt < 2; mt++)
#pragma unroll
            for (int nt = 0; nt < 4; nt++) {
                int n2 = nt >> 1, hb = (nt & 1) * 2;
                mma16816(acc[mt][nt], ah[p][mt], wh[p][n2][hb], wh[p][n2][hb + 1]);
            }
#pragma unroll
        for (int mt = 0; mt < 2; mt++)
#pragma unroll
            for (int nt = 0; nt < 4; nt++) {
                int n2 = nt >> 1, hb = (nt & 1) * 2;
                mma16816(acc[mt][nt], ah[p][mt], wl[p][n2][hb], wl[p][n2][hb + 1]);
            }
#pragma unroll
        for (int mt = 0; mt < 2; mt++)
#pragma unroll
            for (int nt = 0; nt < 4; nt++) {
                int n2 = nt >> 1, hb = (nt & 1) * 2;
                mma16816(acc[mt][nt], al[p][mt], wh[p][n2][hb], wh[p][n2][hb + 1]);
            }
    };

    load(0, 0);
#pragma unroll 1
    for (int c = 0; c < SC; c++) {
        if (c + 1 < SC) {
            load(c + 1, (c + 1) & 1);
            asm volatile("cp.async.wait_group 1;" ::: "memory");   // my chunk-c copies done
        } else {
            asm volatile("cp.async.wait_group 0;" ::: "memory");
        }
        __syncthreads();                 // all threads' chunk-c copies visible
        const __nv_bfloat16* base = smem + (c & 1) * STAGE;
        ldfrags(base, 0, 0);             // ks0 frags
        ldfrags(base, 1, 1);             // ks1 frags issued before ks0 mma burst
        mmas(0);                         // ks1 ldsm latency hidden under these
        mmas(1);
        __syncthreads();                 // compute done before buf overwrite
    }

    // epilogue
    const int r4 = lane >> 2;
    const int c2 = (lane & 3) * 2;
#pragma unroll
    for (int mt = 0; mt < 2; mt++) {
        int mrow = m0 + wm * 32 + mt * 16 + r4;
#pragma unroll
        for (int nt = 0; nt < 4; nt++) {
            int ncol = n0 + wn * 32 + nt * 8 + c2;
            float2 bv = *(const float2*)&bias[ncol];
            float2 o0, o1;
            o0.x = acc[mt][nt][0] + bv.x; o0.y = acc[mt][nt][1] + bv.y;
            o1.x = acc[mt][nt][2] + bv.x; o1.y = acc[mt][nt][3] + bv.y;
            *(float2*)&C[(size_t)mrow * ldc + ncol]       = o0;
            *(float2*)&C[(size_t)(mrow + 8) * ldc + ncol] = o1;
        }
    }
}

// ---------------------------------------------------------------------------
// zflat (round-14 proven): scalar fill, Z staged, coalesced bf162 stores.
// ---------------------------------------------------------------------------
__global__ void __launch_bounds__(64)
zflat_kernel(const float* __restrict__ sparse)
{
    __shared__ __align__(16) float Tt[2][128 * 28];
    __shared__ __align__(16) float ZS[2][380];

    const int w    = threadIdx.x >> 5;
    const int lane = threadIdx.x & 31;
    const size_t b = (size_t)blockIdx.x * 2 + w;
    float* T  = Tt[w];
    float* Z  = ZS[w];
    __nv_bfloat16* arow = g_apack + b * KAP;

    if (lane < 6) {
        arow[890 + lane]       = __float2bfloat16(0.0f);
        arow[ALO + 890 + lane] = __float2bfloat16(0.0f);
    }

    {
        const float* src = g_proj + b * 128;
#pragma unroll
        for (int c = 0; c < 4; c++) { int e = lane + 32 * c; T[e * 28 + 0] = src[e]; }
    }
    for (int i = 1; i < NI; i++) {
        const float* src = sparse + (b * NSP + (i - 1)) * 128;
#pragma unroll
        for (int c = 0; c < 4; c++) { int e = lane + 32 * c; T[e * 28 + i] = src[e]; }
    }
    __syncwarp();

    if (lane < 28) {
        int ti = 0, rem = lane;
        while (rem > ti) { rem -= (ti + 1); ti++; }
        int tj = rem;

        float acc[4][4];
#pragma unroll
        for (int r = 0; r < 4; r++)
#pragma unroll
            for (int c = 0; c < 4; c++) acc[r][c] = 0.0f;

#pragma unroll 4
        for (int e = 0; e < 128; e++) {
            float4 av = *(const float4*)&T[e * 28 + 4 * ti];
            float4 bv = *(const float4*)&T[e * 28 + 4 * tj];
            float a[4]  = {av.x, av.y, av.z, av.w};
            float c4[4] = {bv.x, bv.y, bv.z, bv.w};
#pragma unroll
            for (int r = 0; r < 4; r++)
#pragma unroll
                for (int c = 0; c < 4; c++) acc[r][c] += a[r] * c4[c];
        }

#pragma unroll
        for (int r = 0; r < 4; r++) {
            int i = 4 * ti + r;
            if (i < NI) {
#pragma unroll
                for (int c = 0; c < 4; c++) {
                    int j = 4 * tj + c;
                    if (j <= i) Z[i * (i + 1) / 2 + j] = acc[r][c];
                }
            }
        }
    }
    __syncwarp();

#pragma unroll 2
    for (int t = lane; t < 189; t += 32) {
        float f0 = Z[2 * t], f1 = Z[2 * t + 1];
        __nv_bfloat16 h0, l0, h1, l1;
        bf_split(f0, h0, l0);
        bf_split(f1, h1, l1);
        *(__nv_bfloat162*)(arow + 512 + 2 * t)       = __nv_bfloat162(h0, h1);
        *(__nv_bfloat162*)(arow + ALO + 512 + 2 * t) = __nv_bfloat162(l0, l1);
    }
}

// ---------------------------------------------------------------------------
// launch — __device__ globals never referenced from host code (MODE binding).
// ---------------------------------------------------------------------------
extern "C" void kernel_launch(void* const* d_in, const int* in_sizes, int n_in,
                              void* d_out, int out_size) {
    const float* dense  = (const float*)d_in[0];
    const float* sparse = (const float*)d_in[1];
    const float* Wp     = (const float*)d_in[2];
    const float* bp     = (const float*)d_in[3];
    const float* Wo     = (const float*)d_in[4];
    const float* bo     = (const float*)d_in[5];
    float* out = (float*)d_out;

    cudaFuncSetAttribute(gemm_mma_kernel<16, 512, 0>,
                         cudaFuncAttributeMaxDynamicSharedMemorySize, SMEM_BYTES);
    cudaFuncSetAttribute(gemm_mma_kernel<28, 896, 1>,
                         cudaFuncAttributeMaxDynamicSharedMemorySize, SMEM_BYTES);

    pack_dense_kernel<<<BROWS * DIN / (4 * 256), 256>>>(dense);
    pack_wp_kernel<<<EMB, 256>>>(Wp);
    pack_wo_kernel<<<OUTD, 256>>>(Wo);

    // proj: g_proj[B,128] = dense @ Wp^T + bp   (16 unified K32 chunks)
    gemm_mma_kernel<16, 512, 0><<<dim3(1, BROWS / 128), 512, SMEM_BYTES>>>(bp, nullptr);

    zflat_kernel<<<BROWS / 2, 64>>>(sparse);

    // out: [B,512] = [dense|Ztri] @ Wo^T + bo   (28 unified K32 chunks)
    gemm_mma_kernel<28, 896, 1><<<dim3(OUTD / 128, BROWS / 128), 512, SMEM_BYTES>>>(bo, out);
}

// round 17
// speedup vs baseline: 1.2620x; 1.2620x over previous
#include <cuda_runtime.h>
#include <cuda_fp16.h>
#include <cstdint>

// ---------------- problem constants ----------------
#define BROWS 16384
#define DIN   512
#define NSP   26
#define EMB   128
#define OUTD  512
#define NI    27
#define NTRI  378
#define KAP   1792
#define ALO   896
#define KWO   896           // Wo pack: single fp16 (896)
#define KWP   1024          // Wp pack: [hi(512) | lo(512)]

// ---------------- device scratch (ONLY referenced from device code!) --------
__device__ __align__(16) __half g_apack[BROWS * KAP];   // fp16 exact split: hi|lo
__device__ __align__(16) __half g_wopack[OUTD * KWO];   // fp16 rounded once
__device__ __align__(16) __half g_wppack[EMB * KWP];    // fp16 hi|lo split
__device__ __align__(16) float  g_proj[BROWS * EMB];

// ---------------- helpers ----------------
__device__ __forceinline__ void hf_split(float v, __half& h, __half& l) {
    h = __float2half_rn(v);
    l = __float2half_rn(v - __half2float(h));
}
__device__ __forceinline__ uint32_t smem_u32(const void* p) {
    uint32_t a;
    asm("{ .reg .u64 t; cvta.to.shared.u64 t, %1; cvt.u32.u64 %0, t; }" : "=r"(a) : "l"(p));
    return a;
}
__device__ __forceinline__ void cp_async16(uint32_t s, const void* g) {
    asm volatile("cp.async.cg.shared.global [%0], [%1], 16;" :: "r"(s), "l"(g) : "memory");
}
__device__ __forceinline__ void ldsm_x4(uint32_t* r, uint32_t addr) {
    asm volatile("ldmatrix.sync.aligned.m8n8.x4.shared.b16 {%0,%1,%2,%3}, [%4];"
                 : "=r"(r[0]), "=r"(r[1]), "=r"(r[2]), "=r"(r[3]) : "r"(addr));
}
__device__ __forceinline__ void mma16816(float* c,
                                         const uint32_t* a, uint32_t b0, uint32_t b1) {
    asm volatile("mma.sync.aligned.m16n8k16.row.col.f32.f16.f16.f32 "
                 "{%0,%1,%2,%3}, {%4,%5,%6,%7}, {%8,%9}, {%0,%1,%2,%3};"
                 : "+f"(c[0]), "+f"(c[1]), "+f"(c[2]), "+f"(c[3])
                 : "r"(a[0]), "r"(a[1]), "r"(a[2]), "r"(a[3]), "r"(b0), "r"(b1));
}

// ---------------------------------------------------------------------------
// pack kernels
// ---------------------------------------------------------------------------
__global__ void pack_dense_kernel(const float* __restrict__ dense) {
    size_t t   = (size_t)blockIdx.x * 256 + threadIdx.x;
    size_t row = t >> 7;
    int    c4  = (int)(t & 127) * 4;
    float4 v   = *(const float4*)(dense + row * DIN + c4);
    float  vv[4] = {v.x, v.y, v.z, v.w};
    __half h[4], l[4];
#pragma unroll
    for (int i = 0; i < 4; i++) hf_split(vv[i], h[i], l[i]);
    __half* a = g_apack + row * KAP;
    *(__half2*)(a + c4)           = __half2(h[0], h[1]);
    *(__half2*)(a + c4 + 2)       = __half2(h[2], h[3]);
    *(__half2*)(a + ALO + c4)     = __half2(l[0], l[1]);
    *(__half2*)(a + ALO + c4 + 2) = __half2(l[2], l[3]);
}

__global__ void pack_wo_kernel(const float* __restrict__ Wo) {
    int n = blockIdx.x;
    for (int k = threadIdx.x; k < 896; k += 256) {
        float v = (k < 890) ? Wo[(size_t)n * 890 + k] : 0.0f;
        g_wopack[(size_t)n * KWO + k] = __float2half_rn(v);
    }
}

__global__ void pack_wp_kernel(const float* __restrict__ Wp) {
    int n = blockIdx.x;
    for (int k = threadIdx.x; k < 512; k += 256) {
        float v = Wp[(size_t)n * 512 + k];
        __half h, l;
        hf_split(v, h, l);
        __half* w = g_wppack + (size_t)n * KWP;
        w[k] = h; w[512 + k] = l;
    }
}

#define PADK   40                       // fp16 row stride -> 80B, conflict-free
#define TILE   (128 * PADK)

// ---------------------------------------------------------------------------
// proj GEMM: 3-term fp16 (A exact-split x Wp hi/lo): Ah*Wh + Ah*Wl + Al*Wh.
// Round-14 proven mechanics: 8 warps, 128x128 CTA, 64x32 warp tile, 2-stage.
// ---------------------------------------------------------------------------
#define STAGE4 (4 * TILE)
#define SMEM4  (2 * STAGE4 * 2)         // 81920

__global__ void __launch_bounds__(256, 2)
gemm_proj_kernel(const float* __restrict__ bias)
{
    extern __shared__ __align__(16) __half smem[];

    const __half* __restrict__ A = g_apack;
    const __half* __restrict__ W = g_wppack;
    const int KA = KAP, KW = KWP, KWH = 512, SC = 16;
    float* __restrict__ C = g_proj;
    const int ldc = EMB;

    const int tid  = threadIdx.x;
    const int wid  = tid >> 5;
    const int lane = tid & 31;
    const int wm   = wid >> 2;
    const int wn   = wid & 3;
    const int m0   = blockIdx.y * 128;
    const int n0   = 0;

    float acc[4][4][4];
#pragma unroll
    for (int i = 0; i < 4; i++)
#pragma unroll
        for (int j = 0; j < 4; j++)
#pragma unroll
            for (int q = 0; q < 4; q++) acc[i][j][q] = 0.0f;

    auto load = [&](int c, int buf) {
        const __half* s0 = A + (size_t)m0 * KA + c * 32;
        const __half* s2 = W + (size_t)n0 * KW + c * 32;
        __half* dst = smem + buf * STAGE4;
#pragma unroll
        for (int i = 0; i < 8; i++) {
            int idx  = tid + i * 256;
            int tile = i >> 1;
            int row  = (idx >> 2) & 127;
            int j    = idx & 3;
            const __half* src =
                (tile == 0) ? s0 + (size_t)row * KA :
                (tile == 1) ? s0 + (size_t)row * KA + ALO :
                (tile == 2) ? s2 + (size_t)row * KW :
                              s2 + (size_t)row * KW + KWH;
            cp_async16(smem_u32(dst + tile * TILE + row * PADK + j * 8), src + j * 8);
        }
        asm volatile("cp.async.commit_group;" ::: "memory");
    };

    auto compute = [&](int buf) {
        const __half* base = smem + buf * STAGE4;
#pragma unroll
        for (int ks = 0; ks < 2; ks++) {
            const int aoff = (wm * 64 + (lane & 15)) * PADK + ks * 16 + (lane >> 4) * 8;
            const int boff = (wn * 32 + ((lane >> 4) & 1) * 8 + (lane & 7)) * PADK +
                             ks * 16 + ((lane >> 3) & 1) * 8;
            uint32_t ah[4][4], wh[2][4], wl[2][4];
#pragma unroll
            for (int mt = 0; mt < 4; mt++)
                ldsm_x4(ah[mt], smem_u32(base + 0 * TILE + aoff + mt * 16 * PADK));
#pragma unroll
            for (int n2 = 0; n2 < 2; n2++)
                ldsm_x4(wh[n2], smem_u32(base + 2 * TILE + boff + n2 * 16 * PADK));
#pragma unroll
            for (int n2 = 0; n2 < 2; n2++)
                ldsm_x4(wl[n2], smem_u32(base + 3 * TILE + boff + n2 * 16 * PADK));
#pragma unroll
            for (int mt = 0; mt < 4; mt++)
#pragma unroll
                for (int nt = 0; nt < 4; nt++) {
                    int n2 = nt >> 1, hb = (nt & 1) * 2;
                    mma16816(acc[mt][nt], ah[mt], wh[n2][hb], wh[n2][hb + 1]);
                    mma16816(acc[mt][nt], ah[mt], wl[n2][hb], wl[n2][hb + 1]);
                }
            uint32_t al[4][4];
#pragma unroll
            for (int mt = 0; mt < 4; mt++)
                ldsm_x4(al[mt], smem_u32(base + 1 * TILE + aoff + mt * 16 * PADK));
#pragma unroll
            for (int mt = 0; mt < 4; mt++)
#pragma unroll
                for (int nt = 0; nt < 4; nt++) {
                    int n2 = nt >> 1, hb = (nt & 1) * 2;
                    mma16816(acc[mt][nt], al[mt], wh[n2][hb], wh[n2][hb + 1]);
                }
        }
    };

    load(0, 0);
#pragma unroll 1
    for (int c = 0; c < SC; c++) {
        if (c + 1 < SC) {
            load(c + 1, (c + 1) & 1);
            asm volatile("cp.async.wait_group 1;" ::: "memory");
        } else {
            asm volatile("cp.async.wait_group 0;" ::: "memory");
        }
        __syncthreads();
        compute(c & 1);
        __syncthreads();
    }

    const int r4 = lane >> 2;
    const int c2 = (lane & 3) * 2;
#pragma unroll
    for (int mt = 0; mt < 4; mt++) {
        int mrow = m0 + wm * 64 + mt * 16 + r4;
#pragma unroll
        for (int nt = 0; nt < 4; nt++) {
            int ncol = n0 + wn * 32 + nt * 8 + c2;
            float2 bv = *(const float2*)&bias[ncol];
            float2 o0, o1;
            o0.x = acc[mt][nt][0] + bv.x; o0.y = acc[mt][nt][1] + bv.y;
            o1.x = acc[mt][nt][2] + bv.x; o1.y = acc[mt][nt][3] + bv.y;
            *(float2*)&C[(size_t)mrow * ldc + ncol]       = o0;
            *(float2*)&C[(size_t)(mrow + 8) * ldc + ncol] = o1;
        }
    }
}

// ---------------------------------------------------------------------------
// out GEMM: 2-term fp16 (A exact-split x Wo rounded): Ah*Wh + Al*Wh.
// 3 tiles per stage (Ah, Al, Wh); 2/3 the MMAs, 3/4 the tile traffic.
// ---------------------------------------------------------------------------
#define STAGE3 (3 * TILE)
#define SMEM3  (2 * STAGE3 * 2)         // 61440

__global__ void __launch_bounds__(256, 2)
gemm_out_kernel(const float* __restrict__ bias, float* __restrict__ C)
{
    extern __shared__ __align__(16) __half smem[];

    const __half* __restrict__ A = g_apack;
    const __half* __restrict__ W = g_wopack;
    const int KA = KAP, KW = KWO, SC = 28;
    const int ldc = OUTD;

    const int tid  = threadIdx.x;
    const int wid  = tid >> 5;
    const int lane = tid & 31;
    const int wm   = wid >> 2;
    const int wn   = wid & 3;
    const int m0   = blockIdx.y * 128;
    const int n0   = blockIdx.x * 128;

    float acc[4][4][4];
#pragma unroll
    for (int i = 0; i < 4; i++)
#pragma unroll
        for (int j = 0; j < 4; j++)
#pragma unroll
            for (int q = 0; q < 4; q++) acc[i][j][q] = 0.0f;

    // 3 tiles x 512 uint4 = 1536 tasks over 256 threads (6 each)
    auto load = [&](int c, int buf) {
        const __half* sa = A + (size_t)m0 * KA + c * 32;
        const __half* sw = W + (size_t)n0 * KW + c * 32;
        __half* dst = smem + buf * STAGE3;
#pragma unroll
        for (int i = 0; i < 6; i++) {
            int idx  = tid + i * 256;
            int tile = i >> 1;                  // 0:Ah 1:Al 2:Wh
            int row  = (idx >> 2) & 127;
            int j    = idx & 3;
            const __half* src =
                (tile == 0) ? sa + (size_t)row * KA :
                (tile == 1) ? sa + (size_t)row * KA + ALO :
                              sw + (size_t)row * KW;
            cp_async16(smem_u32(dst + tile * TILE + row * PADK + j * 8), src + j * 8);
        }
        asm volatile("cp.async.commit_group;" ::: "memory");
    };

    auto compute = [&](int buf) {
        const __half* base = smem + buf * STAGE3;
#pragma unroll
        for (int ks = 0; ks < 2; ks++) {
            const int aoff = (wm * 64 + (lane & 15)) * PADK + ks * 16 + (lane >> 4) * 8;
            const int boff = (wn * 32 + ((lane >> 4) & 1) * 8 + (lane & 7)) * PADK +
                             ks * 16 + ((lane >> 3) & 1) * 8;
            uint32_t ah[4][4], wh[2][4];
#pragma unroll
            for (int mt = 0; mt < 4; mt++)
                ldsm_x4(ah[mt], smem_u32(base + 0 * TILE + aoff + mt * 16 * PADK));
#pragma unroll
            for (int n2 = 0; n2 < 2; n2++)
                ldsm_x4(wh[n2], smem_u32(base + 2 * TILE + boff + n2 * 16 * PADK));
#pragma unroll
            for (int mt = 0; mt < 4; mt++)
#pragma unroll
                for (int nt = 0; nt < 4; nt++) {
                    int n2 = nt >> 1, hb = (nt & 1) * 2;
                    mma16816(acc[mt][nt], ah[mt], wh[n2][hb], wh[n2][hb + 1]);
                }
            uint32_t al[4][4];
#pragma unroll
            for (int mt = 0; mt < 4; mt++)
                ldsm_x4(al[mt], smem_u32(base + 1 * TILE + aoff + mt * 16 * PADK));
#pragma unroll
            for (int mt = 0; mt < 4; mt++)
#pragma unroll
                for (int nt = 0; nt < 4; nt++) {
                    int n2 = nt >> 1, hb = (nt & 1) * 2;
                    mma16816(acc[mt][nt], al[mt], wh[n2][hb], wh[n2][hb + 1]);
                }
        }
    };

    load(0, 0);
#pragma unroll 1
    for (int c = 0; c < SC; c++) {
        if (c + 1 < SC) {
            load(c + 1, (c + 1) & 1);
            asm volatile("cp.async.wait_group 1;" ::: "memory");
        } else {
            asm volatile("cp.async.wait_group 0;" ::: "memory");
        }
        __syncthreads();
        compute(c & 1);
        __syncthreads();
    }

    const int r4 = lane >> 2;
    const int c2 = (lane & 3) * 2;
#pragma unroll
    for (int mt = 0; mt < 4; mt++) {
        int mrow = m0 + wm * 64 + mt * 16 + r4;
#pragma unroll
        for (int nt = 0; nt < 4; nt++) {
            int ncol = n0 + wn * 32 + nt * 8 + c2;
            float2 bv = *(const float2*)&bias[ncol];
            float2 o0, o1;
            o0.x = acc[mt][nt][0] + bv.x; o0.y = acc[mt][nt][1] + bv.y;
            o1.x = acc[mt][nt][2] + bv.x; o1.y = acc[mt][nt][3] + bv.y;
            *(float2*)&C[(size_t)mrow * ldc + ncol]       = o0;
            *(float2*)&C[(size_t)(mrow + 8) * ldc + ncol] = o1;
        }
    }
}

// ---------------------------------------------------------------------------
// zflat (round-14 proven): scalar fill, Z staged, coalesced half2 stores.
// ---------------------------------------------------------------------------
__global__ void __launch_bounds__(64)
zflat_kernel(const float* __restrict__ sparse)
{
    __shared__ __align__(16) float Tt[2][128 * 28];
    __shared__ __align__(16) float ZS[2][380];

    const int w    = threadIdx.x >> 5;
    const int lane = threadIdx.x & 31;
    const size_t b = (size_t)blockIdx.x * 2 + w;
    float* T  = Tt[w];
    float* Z  = ZS[w];
    __half* arow = g_apack + b * KAP;

    if (lane < 6) {
        arow[890 + lane]       = __float2half_rn(0.0f);
        arow[ALO + 890 + lane] = __float2half_rn(0.0f);
    }

    {
        const float* src = g_proj + b * 128;
#pragma unroll
        for (int c = 0; c < 4; c++) { int e = lane + 32 * c; T[e * 28 + 0] = src[e]; }
    }
    for (int i = 1; i < NI; i++) {
        const float* src = sparse + (b * NSP + (i - 1)) * 128;
#pragma unroll
        for (int c = 0; c < 4; c++) { int e = lane + 32 * c; T[e * 28 + i] = src[e]; }
    }
    __syncwarp();

    if (lane < 28) {
        int ti = 0, rem = lane;
        while (rem > ti) { rem -= (ti + 1); ti++; }
        int tj = rem;

        float acc[4][4];
#pragma unroll
        for (int r = 0; r < 4; r++)
#pragma unroll
            for (int c = 0; c < 4; c++) acc[r][c] = 0.0f;

#pragma unroll 4
        for (int e = 0; e < 128; e++) {
            float4 av = *(const float4*)&T[e * 28 + 4 * ti];
            float4 bv = *(const float4*)&T[e * 28 + 4 * tj];
            float a[4]  = {av.x, av.y, av.z, av.w};
            float c4[4] = {bv.x, bv.y, bv.z, bv.w};
#pragma unroll
            for (int r = 0; r < 4; r++)
#pragma unroll
                for (int c = 0; c < 4; c++) acc[r][c] += a[r] * c4[c];
        }

#pragma unroll
        for (int r = 0; r < 4; r++) {
            int i = 4 * ti + r;
            if (i < NI) {
#pragma unroll
                for (int c = 0; c < 4; c++) {
                    int j = 4 * tj + c;
                    if (j <= i) Z[i * (i + 1) / 2 + j] = acc[r][c];
                }
            }
        }
    }
    __syncwarp();

#pragma unroll 2
    for (int t = lane; t < 189; t += 32) {
        float f0 = Z[2 * t], f1 = Z[2 * t + 1];
        __half h0, l0, h1, l1;
        hf_split(f0, h0, l0);
        hf_split(f1, h1, l1);
        *(__half2*)(arow + 512 + 2 * t)       = __half2(h0, h1);
        *(__half2*)(arow + ALO + 512 + 2 * t) = __half2(l0, l1);
    }
}

// ---------------------------------------------------------------------------
// launch — __device__ globals never referenced from host code.
// ---------------------------------------------------------------------------
extern "C" void kernel_launch(void* const* d_in, const int* in_sizes, int n_in,
                              void* d_out, int out_size) {
    const float* dense  = (const float*)d_in[0];
    const float* sparse = (const float*)d_in[1];
    const float* Wp     = (const float*)d_in[2];
    const float* bp     = (const float*)d_in[3];
    const float* Wo     = (const float*)d_in[4];
    const float* bo     = (const float*)d_in[5];
    float* out = (float*)d_out;

    cudaFuncSetAttribute(gemm_proj_kernel,
                         cudaFuncAttributeMaxDynamicSharedMemorySize, SMEM4);
    cudaFuncSetAttribute(gemm_out_kernel,
                         cudaFuncAttributeMaxDynamicSharedMemorySize, SMEM3);

    pack_dense_kernel<<<BROWS * DIN / (4 * 256), 256>>>(dense);
    pack_wp_kernel<<<EMB, 256>>>(Wp);
    pack_wo_kernel<<<OUTD, 256>>>(Wo);

    // proj: 3-term fp16 (error ~2^-22) -> g_proj
    gemm_proj_kernel<<<dim3(1, BROWS / 128), 256, SMEM4>>>(bp);

    zflat_kernel<<<BROWS / 2, 64>>>(sparse);

    // out: 2-term fp16 (error ~2.8e-4 from Wo rounding only)
    gemm_out_kernel<<<dim3(OUTD / 128, BROWS / 128), 256, SMEM3>>>(bo, out);
}